// round 16
// baseline (speedup 1.0000x reference)
#include <cuda_runtime.h>
#include <cstdint>

// ---------------------------------------------------------------------------
// DeeProBot MoE, k=1 (one-hot argmax gating) — TF32 HMMA edition, R16.
//   out[n] = relu(x[n] @ W1[e] + b1[e]) @ (W2[e]@Wout) + (b2[e]@Wout + bout)
//   e = argmax(x[n] @ w_gate);  loss = closed form of the two expert counts.
//
// Layer-1 entirely on tensor pipe: k0-7 = W1 (3x k8 MMA, hi/lo split),
// k8 = x8*W8, k9 = 1.0*b1 (3x k4 MMA, hi/lo). Epilogue = relu + dot(wf).
// fold fused into the gate launch as extra blocks.
// ---------------------------------------------------------------------------

#define MAXN 524288
#define NP   (MAXN + 256)

typedef unsigned int       u32;
typedef unsigned long long u64;

__device__ int   g_c0 = 0, g_c1 = 0, g_done = 0;
__device__ int   g_idx0[NP];
__device__ int   g_idx1[NP];
// per token 12 f32: [0..8] = x, [9..11] = 0
__device__ __align__(16) uint4 g_xa0[NP][3];
__device__ __align__(16) uint4 g_xa1[NP][3];
// [e][v][j][k12]: k0-7 = W1, k8 = W1[k=8], k9 = b1, k10-11 = 0
__device__ __align__(16) u32   g_wB[2 * 2 * 128 * 12];
__device__ __align__(16) float2 g_wf[256];    // [e][j] = {wf0, wf1}
__device__ float  g_bf[4];

// ---------------- helpers ----------------
__device__ __forceinline__ u32 rna_tf32(float v) {
    u32 r;
    asm("cvt.rna.tf32.f32 %0, %1;" : "=r"(r) : "f"(v));
    return r;
}
// m16n8k8 tf32: a0:(g,k=s) a1:(g+8,k=s) a2:(g,k=s+4) a3:(g+8,k=s+4)
//               b0:(k=s,n=g) b1:(k=s+4,n=g); c:(g,2s),(g,2s+1),(g+8,2s),(g+8,2s+1)
__device__ __forceinline__ void mma_k8(float* d, u32 a0, u32 a1, u32 a2, u32 a3,
                                       u32 b0, u32 b1) {
    asm volatile(
        "mma.sync.aligned.m16n8k8.row.col.f32.tf32.tf32.f32 "
        "{%0,%1,%2,%3},{%4,%5,%6,%7},{%8,%9},{%0,%1,%2,%3};"
        : "+f"(d[0]), "+f"(d[1]), "+f"(d[2]), "+f"(d[3])
        : "r"(a0), "r"(a1), "r"(a2), "r"(a3), "r"(b0), "r"(b1));
}
// m16n8k4 tf32: a0:(g,k=s) a1:(g+8,k=s); b0:(k=s,n=g)
__device__ __forceinline__ void mma_k4(float* d, u32 a0, u32 a1, u32 b0) {
    asm volatile(
        "mma.sync.aligned.m16n8k4.row.col.f32.tf32.tf32.f32 "
        "{%0,%1,%2,%3},{%4,%5},{%6},{%0,%1,%2,%3};"
        : "+f"(d[0]), "+f"(d[1]), "+f"(d[2]), "+f"(d[3])
        : "r"(a0), "r"(a1), "r"(b0));
}

// ---------------------------------------------------------------------------
// gate_fold_kernel: blocks [0, gb) gate 512 tokens each; blocks [gb, gb+27)
// run the fold (weight prep) path.
// ---------------------------------------------------------------------------
__global__ void __launch_bounds__(256) gate_fold_kernel(
        const float* __restrict__ x,  const float* __restrict__ wg,
        const float* __restrict__ W1, const float* __restrict__ b1,
        const float* __restrict__ W2, const float* __restrict__ b2,
        const float* __restrict__ Wout, const float* __restrict__ bout,
        int N, int gb) {
    const int tid = threadIdx.x;

    if (blockIdx.x >= gb) {
        // ---------------- fold path ----------------
        const int idx = (blockIdx.x - gb) * 256 + tid;
        if (idx < 6144) {
            int k = idx % 12;
            int j = (idx / 12) & 127;
            int v = (idx / 1536) & 1;
            int e = idx / 3072;
            float w = 0.0f;
            if (k <= 8)      w = W1[(e * 9 + k) * 128 + j];
            else if (k == 9) w = b1[e * 128 + j];
            u32 hi = rna_tf32(w);
            if (v) {
                float r = w - __uint_as_float(hi);
                g_wB[idx] = rna_tf32(r);
            } else {
                g_wB[idx] = hi;
            }
        } else if (idx < 6400) {
            int q = idx - 6144;
            int j = q & 127, e = q >> 7;
            float s0 = 0.0f, s1 = 0.0f;
            #pragma unroll
            for (int m = 0; m < 32; ++m) {
                float w2 = W2[(e * 128 + j) * 32 + m];
                s0 = fmaf(w2, Wout[m * 2 + 0], s0);
                s1 = fmaf(w2, Wout[m * 2 + 1], s1);
            }
            g_wf[e * 128 + j] = make_float2(s0, s1);
        } else if (idx < 6404) {
            int q = idx - 6400;
            int e = q >> 1, o = q & 1;
            float s = bout[o];
            #pragma unroll
            for (int m = 0; m < 32; ++m)
                s = fmaf(b2[e * 32 + m], Wout[m * 2 + o], s);
            g_bf[q] = s;
        }
        return;
    }

    // ---------------- gate path: 512 tokens/block ----------------
    __shared__ float sx[4608];
    __shared__ int swc0[8], swc1[8];
    __shared__ int spf0[8], spf1[8];
    __shared__ int sbase0, sbase1;

    const int tok0 = blockIdx.x * 512;
    const int navail = min(512, N - tok0);
    const int nflt = navail * 9;

    {
        const float4* xb = reinterpret_cast<const float4*>(x + (size_t)tok0 * 9);
        float4* s4 = reinterpret_cast<float4*>(sx);
        int nf4 = nflt >> 2;
        for (int i = tid; i < nf4; i += 256) s4[i] = xb[i];
        for (int i = (nf4 << 2) + tid; i < nflt; i += 256)
            sx[i] = x[(size_t)tok0 * 9 + i];
    }
    float wgr[18];
    #pragma unroll
    for (int i = 0; i < 18; ++i) wgr[i] = __ldg(wg + i);
    __syncthreads();

    const int lane = tid & 31, w = tid >> 5;
    unsigned m0[2], m1[2];

    #pragma unroll
    for (int p = 0; p < 2; ++p) {
        int tl = tid + 256 * p;
        bool valid = tl < navail;
        float l0 = 0.0f, l1 = 0.0f;
        #pragma unroll
        for (int d = 0; d < 9; ++d) {
            float v = sx[tl * 9 + d];
            l0 = fmaf(v, wgr[2 * d], l0);
            l1 = fmaf(v, wgr[2 * d + 1], l1);
        }
        unsigned mv = __ballot_sync(0xffffffffu, valid);
        m1[p] = __ballot_sync(0xffffffffu, valid && (l1 > l0));
        m0[p] = mv & ~m1[p];
    }
    if (lane == 0) {
        swc0[w] = __popc(m0[0]) + __popc(m0[1]);
        swc1[w] = __popc(m1[0]) + __popc(m1[1]);
    }
    __syncthreads();
    if (tid == 0) {
        int t0 = 0, t1 = 0;
        #pragma unroll
        for (int i = 0; i < 8; ++i) {
            spf0[i] = t0; t0 += swc0[i];
            spf1[i] = t1; t1 += swc1[i];
        }
        sbase0 = atomicAdd(&g_c0, t0);
        sbase1 = atomicAdd(&g_c1, t1);
    }
    __syncthreads();

    int off0 = sbase0 + spf0[w];
    int off1 = sbase1 + spf1[w];
    const unsigned below = (1u << lane) - 1u;
    #pragma unroll
    for (int p = 0; p < 2; ++p) {
        int tl = tid + 256 * p;
        int t  = tok0 + tl;
        bool in1 = (m1[p] >> lane) & 1u;
        bool in0 = (m0[p] >> lane) & 1u;
        if (in0 | in1) {
            float v[9];
            #pragma unroll
            for (int d = 0; d < 9; ++d) v[d] = sx[tl * 9 + d];
            int pos = in1 ? (off1 + __popc(m1[p] & below))
                          : (off0 + __popc(m0[p] & below));
            uint4* dst = in1 ? g_xa1[pos] : g_xa0[pos];
            if (in1) g_idx1[pos] = t; else g_idx0[pos] = t;
            dst[0] = make_uint4(__float_as_uint(v[0]), __float_as_uint(v[1]),
                                __float_as_uint(v[2]), __float_as_uint(v[3]));
            dst[1] = make_uint4(__float_as_uint(v[4]), __float_as_uint(v[5]),
                                __float_as_uint(v[6]), __float_as_uint(v[7]));
            dst[2] = make_uint4(__float_as_uint(v[8]), 0u, 0u, 0u);
        }
        off0 += __popc(m0[p]);
        off1 += __popc(m1[p]);
    }
}

// ---------------------------------------------------------------------------
// moe_loss: 296 blocks x 128 threads. Expert-dedicated warps; B fragments
// (k8 and k4 blocks) hoisted to registers; software-pipelined A loads;
// epilogue = relu + dot(wf) only (x8/b1 live in the MMA).
// ---------------------------------------------------------------------------
__global__ void __launch_bounds__(128, 2) moe_loss(float* __restrict__ out,
                                                   int N, int out_size) {
    __shared__ u32    sB[2 * 2 * 128 * 12];   // 24KB, stride-12 (bank-clean)
    __shared__ float4 sWF[128];               // [e*64 + t*4+s] wf pairs

    const int tid = threadIdx.x, wid = tid >> 5, lane = tid & 31;
    const int c0 = g_c0, c1 = g_c1;

    if (blockIdx.x == 0 && tid == 0 && out_size > 2 * N) {
        double cc1  = (double)c1;
        double cc0  = (double)N - cc1;
        double mean = 0.5 * (cc0 + cc1);
        double d    = cc0 - cc1;
        double cv   = (0.5 * d * d) / (mean * mean + 1e-10);
        out[out_size - 1] = (float)(0.02 * cv);
    }

    {
        const uint4* src = reinterpret_cast<const uint4*>(g_wB);
        uint4* dst = reinterpret_cast<uint4*>(sB);
        #pragma unroll
        for (int i = tid; i < 1536; i += 128) dst[i] = src[i];
        const float4* wf4 = reinterpret_cast<const float4*>(g_wf);
        sWF[tid] = wf4[tid];
    }
    __syncthreads();

    const int nt0 = (c0 + 15) >> 4;
    const int nt1 = (c1 + 15) >> 4;
    const int ntiles = nt0 + nt1;
    const int Wtot = gridDim.x * 4;
    const int gw   = blockIdx.x * 4 + wid;

    // proportional warp->expert partition
    int W0 = (int)(((u64)Wtot * (u64)nt0) / (u64)(ntiles > 0 ? ntiles : 1));
    if (nt0 > 0 && W0 == 0) W0 = 1;
    if (nt1 > 0 && W0 == Wtot) W0 = Wtot - 1;

    int e, ti, tstride, ntE, cnt;
    const int* __restrict__ list;
    const float* __restrict__ xa;
    if (gw < W0) {
        e = 0; ti = gw; tstride = W0; ntE = nt0; cnt = c0;
        list = g_idx0; xa = reinterpret_cast<const float*>(g_xa0);
    } else {
        e = 1; ti = gw - W0; tstride = Wtot - W0; ntE = nt1; cnt = c1;
        list = g_idx1; xa = reinterpret_cast<const float*>(g_xa1);
    }

    const int n = lane >> 2;      // row group / B col group
    const int s = lane & 3;       // k selector

    // ---- hoist B fragments (this expert only), k8 blocks + k4 block ----
    u32 bF[16][4];                // k0-7 hi (2) + lo (2)
    u32 bH[16][2];                // k8-11 hi, lo  (k8=W8, k9=b1)
    {
        const u32* Bh = sB + (e * 2 + 0) * 1536;
        const u32* Bl = sB + (e * 2 + 1) * 1536;
        #pragma unroll
        for (int t = 0; t < 16; ++t) {
            int jb = (t * 8 + n) * 12;
            bF[t][0] = Bh[jb + s];
            bF[t][1] = Bh[jb + 4 + s];
            bF[t][2] = Bl[jb + s];
            bF[t][3] = Bl[jb + 4 + s];
            bH[t][0] = Bh[jb + 8 + s];
            bH[t][1] = Bl[jb + 8 + s];
        }
    }
    const float4* sWFe = sWF + e * 64;
    const float bf0 = g_bf[2 * e], bf1 = g_bf[2 * e + 1];
    const u32 K1 = (s == 1) ? 0x3F800000u : 0u;   // bias column: 1.0 at k=9
    float2* out2 = reinterpret_cast<float2*>(out);

    if (ti >= ntE) goto done;

    {
        // ---- software-pipelined tile loop ----
        float vA0, vA1, vB0, vB1, x8A, x8B;
        {
            int start = ti << 4;
            int pA = min(start + n,     cnt - 1) * 12;
            int pB = min(start + n + 8, cnt - 1) * 12;
            vA0 = __ldg(xa + pA + s); vA1 = __ldg(xa + pA + 4 + s);
            vB0 = __ldg(xa + pB + s); vB1 = __ldg(xa + pB + 4 + s);
            x8A = __ldg(xa + pA + 8); x8B = __ldg(xa + pB + 8);
        }

        while (true) {
            const int start = ti << 4;
            const int tnext = ti + tstride;
            const bool haveN = tnext < ntE;

            // tf32 hi/lo split in registers (k0-7)
            u32 ah0 = rna_tf32(vA0), ah1 = rna_tf32(vB0);
            u32 ah2 = rna_tf32(vA1), ah3 = rna_tf32(vB1);
            u32 al0 = rna_tf32(vA0 - __uint_as_float(ah0));
            u32 al1 = rna_tf32(vB0 - __uint_as_float(ah1));
            u32 al2 = rna_tf32(vA1 - __uint_as_float(ah2));
            u32 al3 = rna_tf32(vB1 - __uint_as_float(ah3));
            // k4 block A frags: {x8, 1.0, 0, 0}
            u32 x8h0 = rna_tf32(x8A), x8h1 = rna_tf32(x8B);
            u32 ag0 = (s == 0) ? x8h0 : K1;
            u32 ag1 = (s == 0) ? x8h1 : K1;
            u32 am0 = (s == 0) ? rna_tf32(x8A - __uint_as_float(x8h0)) : 0u;
            u32 am1 = (s == 0) ? rna_tf32(x8B - __uint_as_float(x8h1)) : 0u;

            float acc[16][4];
            #pragma unroll
            for (int t = 0; t < 16; ++t) {
                acc[t][0] = 0.f; acc[t][1] = 0.f; acc[t][2] = 0.f; acc[t][3] = 0.f;
            }
            #pragma unroll
            for (int t = 0; t < 16; ++t) {
                mma_k8(acc[t], ah0, ah1, ah2, ah3, bF[t][0], bF[t][1]);   // hi*hi
                mma_k8(acc[t], al0, al1, al2, al3, bF[t][0], bF[t][1]);   // lo*hi
                mma_k8(acc[t], ah0, ah1, ah2, ah3, bF[t][2], bF[t][3]);   // hi*lo
                mma_k4(acc[t], ag0, ag1, bH[t][0]);                       // kH hi*hi
                mma_k4(acc[t], am0, am1, bH[t][0]);                       // kH lo*hi
                mma_k4(acc[t], ag0, ag1, bH[t][1]);                       // kH hi*lo
            }

            // prefetch next tile's A while MMAs drain
            if (haveN) {
                int st2 = tnext << 4;
                int pA = min(st2 + n,     cnt - 1) * 12;
                int pB = min(st2 + n + 8, cnt - 1) * 12;
                vA0 = __ldg(xa + pA + s); vA1 = __ldg(xa + pA + 4 + s);
                vB0 = __ldg(xa + pB + s); vB1 = __ldg(xa + pB + 4 + s);
                x8A = __ldg(xa + pA + 8); x8B = __ldg(xa + pB + 8);
            }

            // ---- epilogue: relu + dot(wf), quad reduce ----
            float o0a = 0.f, o1a = 0.f, o0b = 0.f, o1b = 0.f;
            #pragma unroll
            for (int t = 0; t < 16; ++t) {
                float4 wf = sWFe[t * 4 + s];
                float h;
                h = fmaxf(acc[t][0], 0.f); o0a = fmaf(h, wf.x, o0a); o1a = fmaf(h, wf.y, o1a);
                h = fmaxf(acc[t][1], 0.f); o0a = fmaf(h, wf.z, o0a); o1a = fmaf(h, wf.w, o1a);
                h = fmaxf(acc[t][2], 0.f); o0b = fmaf(h, wf.x, o0b); o1b = fmaf(h, wf.y, o1b);
                h = fmaxf(acc[t][3], 0.f); o0b = fmaf(h, wf.z, o0b); o1b = fmaf(h, wf.w, o1b);
            }
            #pragma unroll
            for (int sh = 1; sh <= 2; sh <<= 1) {
                o0a += __shfl_xor_sync(0xffffffffu, o0a, sh);
                o1a += __shfl_xor_sync(0xffffffffu, o1a, sh);
                o0b += __shfl_xor_sync(0xffffffffu, o0b, sh);
                o1b += __shfl_xor_sync(0xffffffffu, o1b, sh);
            }
            if (s == 0) {
                int i0 = start + n, i1 = start + n + 8;
                if (i0 < cnt) out2[__ldg(list + i0)] = make_float2(o0a + bf0, o1a + bf1);
                if (i1 < cnt) out2[__ldg(list + i1)] = make_float2(o0b + bf0, o1b + bf1);
            }

            if (!haveN) break;
            ti = tnext;
        }
    }

done:
    // reset state for next graph replay
    __syncthreads();
    if (tid == 0) {
        int d = atomicAdd(&g_done, 1);
        if (d == gridDim.x - 1) { g_c0 = 0; g_c1 = 0; g_done = 0; }
    }
}

// ---------------------------------------------------------------------------
// Inputs: num_prop, cat_prop, w_gate, W1, b1, W2, b2, Wout, bout, k
// ---------------------------------------------------------------------------
extern "C" void kernel_launch(void* const* d_in, const int* in_sizes, int n_in,
                              void* d_out, int out_size) {
    const float* x    = (const float*)d_in[0];
    const float* wg   = (const float*)d_in[2];
    const float* W1   = (const float*)d_in[3];
    const float* b1   = (const float*)d_in[4];
    const float* W2   = (const float*)d_in[5];
    const float* b2   = (const float*)d_in[6];
    const float* Wout = (const float*)d_in[7];
    const float* bout = (const float*)d_in[8];
    float* out = (float*)d_out;

    int N  = in_sizes[0] / 9;
    int gb = (N + 511) / 512;

    gate_fold_kernel<<<gb + 27, 256>>>(x, wg, W1, b1, W2, b2, Wout, bout, N, gb);
    moe_loss<<<296, 128>>>(out, N, out_size);
}

// round 17
// speedup vs baseline: 1.1724x; 1.1724x over previous
#include <cuda_runtime.h>
#include <cstdint>

// ---------------------------------------------------------------------------
// DeeProBot MoE, k=1 (one-hot argmax gating) — TF32 HMMA edition, R17.
//   out[n] = relu(x[n] @ W1[e] + b1[e]) @ (W2[e]@Wout) + (b2[e]@Wout + bout)
//   e = argmax(x[n] @ w_gate);  loss = closed form of the two expert counts.
//
// R15 math restored (3x k8 tf32 MMA hi/lo for k0-7; x8, b1 exact in fp32
// epilogue — fma pipe overlaps the tensor pipe). R17 change: B fragments
// read from smem per tile (not hoisted) to cut regs -> 3 CTAs/SM (12 warps)
// so MMA phases of different warps overlap and the tensor pipe saturates.
// gate+fold fused in one launch.
// ---------------------------------------------------------------------------

#define MAXN 524288
#define NP   (MAXN + 256)

typedef unsigned int       u32;
typedef unsigned long long u64;

__device__ int   g_c0 = 0, g_c1 = 0, g_done = 0;
__device__ int   g_idx0[NP];
__device__ int   g_idx1[NP];
// per token 12 f32: [0..8] = x, [9..11] = 0
__device__ __align__(16) uint4 g_xa0[NP][3];
__device__ __align__(16) uint4 g_xa1[NP][3];
__device__ __align__(16) u32   g_wB[2 * 2 * 128 * 12];  // [e][v][j][k12], k>=8 zero
__device__ __align__(16) float2 g_wf[256];    // [e][j] = {wf0, wf1}
__device__ __align__(8)  float2 g_b1f[128];   // [e][j/2] b1 pairs
__device__ __align__(8)  float2 g_w8f[128];   // [e][j/2] W1[k=8] pairs
__device__ float  g_bf[4];

// ---------------- helpers ----------------
__device__ __forceinline__ u32 rna_tf32(float v) {
    u32 r;
    asm("cvt.rna.tf32.f32 %0, %1;" : "=r"(r) : "f"(v));
    return r;
}
__device__ __forceinline__ void mma_k8(float* d, u32 a0, u32 a1, u32 a2, u32 a3,
                                       u32 b0, u32 b1) {
    asm volatile(
        "mma.sync.aligned.m16n8k8.row.col.f32.tf32.tf32.f32 "
        "{%0,%1,%2,%3},{%4,%5,%6,%7},{%8,%9},{%0,%1,%2,%3};"
        : "+f"(d[0]), "+f"(d[1]), "+f"(d[2]), "+f"(d[3])
        : "r"(a0), "r"(a1), "r"(a2), "r"(a3), "r"(b0), "r"(b1));
}

// ---------------------------------------------------------------------------
// gate_fold_kernel: blocks [0, gb) gate 512 tokens; blocks [gb, gb+27) fold.
// ---------------------------------------------------------------------------
__global__ void __launch_bounds__(256) gate_fold_kernel(
        const float* __restrict__ x,  const float* __restrict__ wg,
        const float* __restrict__ W1, const float* __restrict__ b1,
        const float* __restrict__ W2, const float* __restrict__ b2,
        const float* __restrict__ Wout, const float* __restrict__ bout,
        int N, int gb) {
    const int tid = threadIdx.x;

    if (blockIdx.x >= gb) {
        // ---------------- fold path ----------------
        const int idx = (blockIdx.x - gb) * 256 + tid;
        if (idx < 6144) {
            int k = idx % 12;
            int j = (idx / 12) & 127;
            int v = (idx / 1536) & 1;
            int e = idx / 3072;
            float w = (k < 8) ? W1[(e * 9 + k) * 128 + j] : 0.0f;
            u32 hi = rna_tf32(w);
            if (v) {
                float r = w - __uint_as_float(hi);
                g_wB[idx] = rna_tf32(r);
            } else {
                g_wB[idx] = hi;
            }
        } else if (idx < 6400) {
            int q = idx - 6144;
            int j = q & 127, e = q >> 7;
            float s0 = 0.0f, s1 = 0.0f;
            #pragma unroll
            for (int m = 0; m < 32; ++m) {
                float w2 = W2[(e * 128 + j) * 32 + m];
                s0 = fmaf(w2, Wout[m * 2 + 0], s0);
                s1 = fmaf(w2, Wout[m * 2 + 1], s1);
            }
            g_wf[e * 128 + j] = make_float2(s0, s1);
        } else if (idx < 6404) {
            int q = idx - 6400;
            int e = q >> 1, o = q & 1;
            float s = bout[o];
            #pragma unroll
            for (int m = 0; m < 32; ++m)
                s = fmaf(b2[e * 32 + m], Wout[m * 2 + o], s);
            g_bf[q] = s;
        } else if (idx < 6532) {
            int q = idx - 6404;          // b1 pairs
            g_b1f[q] = make_float2(b1[2 * q], b1[2 * q + 1]);
        } else if (idx < 6660) {
            int q = idx - 6532;          // W1[k=8] pairs
            int e = q >> 6, j = (q & 63) * 2;
            g_w8f[q] = make_float2(W1[(e * 9 + 8) * 128 + j],
                                   W1[(e * 9 + 8) * 128 + j + 1]);
        }
        return;
    }

    // ---------------- gate path: 512 tokens/block ----------------
    __shared__ float sx[4608];
    __shared__ int swc0[8], swc1[8];
    __shared__ int spf0[8], spf1[8];
    __shared__ int sbase0, sbase1;

    const int tok0 = blockIdx.x * 512;
    const int navail = min(512, N - tok0);
    const int nflt = navail * 9;

    {
        const float4* xb = reinterpret_cast<const float4*>(x + (size_t)tok0 * 9);
        float4* s4 = reinterpret_cast<float4*>(sx);
        int nf4 = nflt >> 2;
        for (int i = tid; i < nf4; i += 256) s4[i] = xb[i];
        for (int i = (nf4 << 2) + tid; i < nflt; i += 256)
            sx[i] = x[(size_t)tok0 * 9 + i];
    }
    float wgr[18];
    #pragma unroll
    for (int i = 0; i < 18; ++i) wgr[i] = __ldg(wg + i);
    __syncthreads();

    const int lane = tid & 31, w = tid >> 5;
    unsigned m0[2], m1[2];

    #pragma unroll
    for (int p = 0; p < 2; ++p) {
        int tl = tid + 256 * p;
        bool valid = tl < navail;
        float l0 = 0.0f, l1 = 0.0f;
        #pragma unroll
        for (int d = 0; d < 9; ++d) {
            float v = sx[tl * 9 + d];
            l0 = fmaf(v, wgr[2 * d], l0);
            l1 = fmaf(v, wgr[2 * d + 1], l1);
        }
        unsigned mv = __ballot_sync(0xffffffffu, valid);
        m1[p] = __ballot_sync(0xffffffffu, valid && (l1 > l0));
        m0[p] = mv & ~m1[p];
    }
    if (lane == 0) {
        swc0[w] = __popc(m0[0]) + __popc(m0[1]);
        swc1[w] = __popc(m1[0]) + __popc(m1[1]);
    }
    __syncthreads();
    if (tid == 0) {
        int t0 = 0, t1 = 0;
        #pragma unroll
        for (int i = 0; i < 8; ++i) {
            spf0[i] = t0; t0 += swc0[i];
            spf1[i] = t1; t1 += swc1[i];
        }
        sbase0 = atomicAdd(&g_c0, t0);
        sbase1 = atomicAdd(&g_c1, t1);
    }
    __syncthreads();

    int off0 = sbase0 + spf0[w];
    int off1 = sbase1 + spf1[w];
    const unsigned below = (1u << lane) - 1u;
    #pragma unroll
    for (int p = 0; p < 2; ++p) {
        int tl = tid + 256 * p;
        int t  = tok0 + tl;
        bool in1 = (m1[p] >> lane) & 1u;
        bool in0 = (m0[p] >> lane) & 1u;
        if (in0 | in1) {
            float v[9];
            #pragma unroll
            for (int d = 0; d < 9; ++d) v[d] = sx[tl * 9 + d];
            int pos = in1 ? (off1 + __popc(m1[p] & below))
                          : (off0 + __popc(m0[p] & below));
            uint4* dst = in1 ? g_xa1[pos] : g_xa0[pos];
            if (in1) g_idx1[pos] = t; else g_idx0[pos] = t;
            dst[0] = make_uint4(__float_as_uint(v[0]), __float_as_uint(v[1]),
                                __float_as_uint(v[2]), __float_as_uint(v[3]));
            dst[1] = make_uint4(__float_as_uint(v[4]), __float_as_uint(v[5]),
                                __float_as_uint(v[6]), __float_as_uint(v[7]));
            dst[2] = make_uint4(__float_as_uint(v[8]), 0u, 0u, 0u);
        }
        off0 += __popc(m0[p]);
        off1 += __popc(m1[p]);
    }
}

// ---------------------------------------------------------------------------
// moe_loss: 444 blocks x 128 threads, 3 CTAs/SM (reg-trimmed: B frags from
// smem per tile). Expert-dedicated warps, software-pipelined A loads,
// fp32 epilogue (x8 rank-1 + b1 + relu + dot(wf)) overlapping tensor pipe.
// ---------------------------------------------------------------------------
__global__ void __launch_bounds__(128, 3) moe_loss(float* __restrict__ out,
                                                   int N, int out_size) {
    __shared__ u32    sB[2 * 2 * 128 * 12];   // 24KB, stride-12 (bank-clean)
    __shared__ float4 sWF[128];               // [e*64 + t*4+s] wf pairs
    __shared__ float4 sAux[128];              // {b1.x,b1.y,w8.x,w8.y}

    const int tid = threadIdx.x, wid = tid >> 5, lane = tid & 31;
    const int c0 = g_c0, c1 = g_c1;

    if (blockIdx.x == 0 && tid == 0 && out_size > 2 * N) {
        double cc1  = (double)c1;
        double cc0  = (double)N - cc1;
        double mean = 0.5 * (cc0 + cc1);
        double d    = cc0 - cc1;
        double cv   = (0.5 * d * d) / (mean * mean + 1e-10);
        out[out_size - 1] = (float)(0.02 * cv);
    }

    {
        const uint4* src = reinterpret_cast<const uint4*>(g_wB);
        uint4* dst = reinterpret_cast<uint4*>(sB);
        #pragma unroll
        for (int i = tid; i < 1536; i += 128) dst[i] = src[i];
        const float4* wf4 = reinterpret_cast<const float4*>(g_wf);
        sWF[tid] = wf4[tid];
        float2 bb = g_b1f[tid];
        float2 w8 = g_w8f[tid];
        sAux[tid] = make_float4(bb.x, bb.y, w8.x, w8.y);
    }
    __syncthreads();

    const int nt0 = (c0 + 15) >> 4;
    const int nt1 = (c1 + 15) >> 4;
    const int ntiles = nt0 + nt1;
    const int Wtot = gridDim.x * 4;
    const int gw   = blockIdx.x * 4 + wid;

    // proportional warp->expert partition
    int W0 = (int)(((u64)Wtot * (u64)nt0) / (u64)(ntiles > 0 ? ntiles : 1));
    if (nt0 > 0 && W0 == 0) W0 = 1;
    if (nt1 > 0 && W0 == Wtot) W0 = Wtot - 1;

    int e, ti, tstride, ntE, cnt;
    const int* __restrict__ list;
    const float* __restrict__ xa;
    if (gw < W0) {
        e = 0; ti = gw; tstride = W0; ntE = nt0; cnt = c0;
        list = g_idx0; xa = reinterpret_cast<const float*>(g_xa0);
    } else {
        e = 1; ti = gw - W0; tstride = Wtot - W0; ntE = nt1; cnt = c1;
        list = g_idx1; xa = reinterpret_cast<const float*>(g_xa1);
    }

    const int n = lane >> 2;      // row group / B col group
    const int s = lane & 3;       // k selector

    const u32* __restrict__ Bh = sB + (e * 2 + 0) * 1536;
    const u32* __restrict__ Bl = sB + (e * 2 + 1) * 1536;
    const float4* sWFe  = sWF  + e * 64;
    const float4* sAuxe = sAux + e * 64;
    const float bf0 = g_bf[2 * e], bf1 = g_bf[2 * e + 1];
    float2* out2 = reinterpret_cast<float2*>(out);

    if (ti >= ntE) goto done;

    {
        // ---- software-pipelined tile loop ----
        float vA0, vA1, vB0, vB1, x8A, x8B;
        {
            int start = ti << 4;
            int pA = min(start + n,     cnt - 1) * 12;
            int pB = min(start + n + 8, cnt - 1) * 12;
            vA0 = __ldg(xa + pA + s); vA1 = __ldg(xa + pA + 4 + s);
            vB0 = __ldg(xa + pB + s); vB1 = __ldg(xa + pB + 4 + s);
            x8A = __ldg(xa + pA + 8); x8B = __ldg(xa + pB + 8);
        }

        while (true) {
            const int start = ti << 4;
            const int tnext = ti + tstride;
            const bool haveN = tnext < ntE;

            // tf32 hi/lo split in registers (k0-7)
            u32 ah0 = rna_tf32(vA0), ah1 = rna_tf32(vB0);
            u32 ah2 = rna_tf32(vA1), ah3 = rna_tf32(vB1);
            u32 al0 = rna_tf32(vA0 - __uint_as_float(ah0));
            u32 al1 = rna_tf32(vB0 - __uint_as_float(ah1));
            u32 al2 = rna_tf32(vA1 - __uint_as_float(ah2));
            u32 al3 = rna_tf32(vB1 - __uint_as_float(ah3));
            const float cx8A = x8A, cx8B = x8B;

            float acc[16][4];
            #pragma unroll
            for (int t = 0; t < 16; ++t) {
                acc[t][0] = 0.f; acc[t][1] = 0.f; acc[t][2] = 0.f; acc[t][3] = 0.f;
            }
            #pragma unroll
            for (int t = 0; t < 16; ++t) {
                int jb = (t * 8 + n) * 12;
                u32 b0 = Bh[jb + s], b1v = Bh[jb + 4 + s];
                u32 b2 = Bl[jb + s], b3v = Bl[jb + 4 + s];
                mma_k8(acc[t], ah0, ah1, ah2, ah3, b0, b1v);   // hi*hi
                mma_k8(acc[t], al0, al1, al2, al3, b0, b1v);   // lo*hi
                mma_k8(acc[t], ah0, ah1, ah2, ah3, b2, b3v);   // hi*lo
            }

            // prefetch next tile's A while MMAs drain
            if (haveN) {
                int st2 = tnext << 4;
                int pA = min(st2 + n,     cnt - 1) * 12;
                int pB = min(st2 + n + 8, cnt - 1) * 12;
                vA0 = __ldg(xa + pA + s); vA1 = __ldg(xa + pA + 4 + s);
                vB0 = __ldg(xa + pB + s); vB1 = __ldg(xa + pB + 4 + s);
                x8A = __ldg(xa + pA + 8); x8B = __ldg(xa + pB + 8);
            }

            // ---- epilogue: + x8*W8 + b1 (fp32), relu, dot(wf), reduce ----
            float o0a = 0.f, o1a = 0.f, o0b = 0.f, o1b = 0.f;
            #pragma unroll
            for (int t = 0; t < 16; ++t) {
                float4 wf = sWFe[t * 4 + s];
                float4 ax = sAuxe[t * 4 + s];
                float h;
                h = fmaxf(fmaf(cx8A, ax.z, acc[t][0]) + ax.x, 0.f);
                o0a = fmaf(h, wf.x, o0a); o1a = fmaf(h, wf.y, o1a);
                h = fmaxf(fmaf(cx8A, ax.w, acc[t][1]) + ax.y, 0.f);
                o0a = fmaf(h, wf.z, o0a); o1a = fmaf(h, wf.w, o1a);
                h = fmaxf(fmaf(cx8B, ax.z, acc[t][2]) + ax.x, 0.f);
                o0b = fmaf(h, wf.x, o0b); o1b = fmaf(h, wf.y, o1b);
                h = fmaxf(fmaf(cx8B, ax.w, acc[t][3]) + ax.y, 0.f);
                o0b = fmaf(h, wf.z, o0b); o1b = fmaf(h, wf.w, o1b);
            }
            #pragma unroll
            for (int sh = 1; sh <= 2; sh <<= 1) {
                o0a += __shfl_xor_sync(0xffffffffu, o0a, sh);
                o1a += __shfl_xor_sync(0xffffffffu, o1a, sh);
                o0b += __shfl_xor_sync(0xffffffffu, o0b, sh);
                o1b += __shfl_xor_sync(0xffffffffu, o1b, sh);
            }
            if (s == 0) {
                int i0 = start + n, i1 = start + n + 8;
                if (i0 < cnt) out2[__ldg(list + i0)] = make_float2(o0a + bf0, o1a + bf1);
                if (i1 < cnt) out2[__ldg(list + i1)] = make_float2(o0b + bf0, o1b + bf1);
            }

            if (!haveN) break;
            ti = tnext;
        }
    }

done:
    // reset state for next graph replay
    __syncthreads();
    if (tid == 0) {
        int d = atomicAdd(&g_done, 1);
        if (d == gridDim.x - 1) { g_c0 = 0; g_c1 = 0; g_done = 0; }
    }
}

// ---------------------------------------------------------------------------
// Inputs: num_prop, cat_prop, w_gate, W1, b1, W2, b2, Wout, bout, k
// ---------------------------------------------------------------------------
extern "C" void kernel_launch(void* const* d_in, const int* in_sizes, int n_in,
                              void* d_out, int out_size) {
    const float* x    = (const float*)d_in[0];
    const float* wg   = (const float*)d_in[2];
    const float* W1   = (const float*)d_in[3];
    const float* b1   = (const float*)d_in[4];
    const float* W2   = (const float*)d_in[5];
    const float* b2   = (const float*)d_in[6];
    const float* Wout = (const float*)d_in[7];
    const float* bout = (const float*)d_in[8];
    float* out = (float*)d_out;

    int N  = in_sizes[0] / 9;
    int gb = (N + 511) / 512;

    gate_fold_kernel<<<gb + 27, 256>>>(x, wg, W1, b1, W2, b2, Wout, bout, N, gb);
    moe_loss<<<444, 128>>>(out, N, out_size);
}